// round 6
// baseline (speedup 1.0000x reference)
#include <cuda_runtime.h>
#include <math.h>

#define BB   256     // batch
#define DM   512     // d_model
#define NV   1376    // n_vars
#define Gm   64      // batch rows per block in embed kernel (single wave: 4*96=384 blocks)
#define MAXS 128     // max slots supported (actual S = 96)

// ---------------- device-global scratch (no allocations allowed) ----------------
__device__ int g_S, g_total;
__device__ int g_c[MAXS], g_L[MAXS], g_k[MAXS], g_off[MAXS];
__device__ float g_pe[MAXS * DM];

// ---------------- setup: block 0 = plan, blocks 1..MAXS = positional emb -------
__global__ void setup_kernel(const int* __restrict__ seg) {
    if (blockIdx.x == 0) {
        __shared__ int sc[MAXS], sL[MAXS], sk[MAXS], sPl[MAXS], soff[MAXS];
        __shared__ int sFirstNeg, sS;
        int tid = threadIdx.x;
        if (tid == 0) { sFirstNeg = NV; sS = 0; }
        __syncthreads();
        // first -1 breaks validity (input has none, but honor the semantics)
        for (int t = tid; t < NV; t += blockDim.x)
            if (seg[t] < 0) atomicMin(&sFirstNeg, t);
        __syncthreads();
        int validN = sFirstNeg;
        // segment starts; consecutive ids => id is the slot index
        for (int t = tid; t < validN; t += blockDim.x) {
            int v = seg[t];
            int prev = (t == 0) ? -2 : seg[t - 1];
            if (v != prev) sc[v] = t;
            atomicMax(&sS, v + 1);
        }
        __syncthreads();
        int S = sS;
        const int PL[4] = {5, 10, 17, 24};
        for (int s = tid; s < S; s += blockDim.x) {
            int cs = sc[s];
            int L = ((s + 1 < S) ? sc[s + 1] : validN) - cs;
            int bestk = 0, bd = abs(L - PL[0]);
#pragma unroll
            for (int k = 1; k < 4; k++) {
                int dd = abs(L - PL[k]);
                if (dd < bd) { bd = dd; bestk = k; }   // strict < keeps first on tie (argmin)
            }
            sL[s] = L; sk[s] = bestk; sPl[s] = PL[bestk];
        }
        __syncthreads();
        if (tid == 0) {
            int acc = 0;
            for (int s = 0; s < S; s++) { soff[s] = acc; acc += sPl[s]; }
            g_total = acc;
            g_S = S;
        }
        __syncthreads();
        for (int s = tid; s < S; s += blockDim.x) {
            g_c[s] = sc[s]; g_L[s] = sL[s]; g_k[s] = sk[s]; g_off[s] = soff[s];
        }
    } else {
        // sin/cos positional embedding table: pe[s, 2j] = sin(s*f_j), pe[s, 2j+1] = cos
        int s = blockIdx.x - 1;
        int j = threadIdx.x;                       // 0..255
        float freq = expf(-(float)(2 * j) * (logf(10000.0f) / (float)DM));
        float sv, cv;
        sincosf((float)s * freq, &sv, &cv);
        g_pe[s * DM + 2 * j]     = sv;
        g_pe[s * DM + 2 * j + 1] = cv;
    }
}

// ---------------- main embedding -----------------------------------------------
// One block = (slot s, 64 batch rows). 256 threads, each owns 2 output channels
// d = 2*tid, d+1. W rows in registers as packed f32x2 pairs; patch values staged
// in shared padded to a multiple of 4 so the inner loop reads LDS.128 straight
// into fma.rn.f32x2 operands (no MOV packing). 4 independent accumulator chains.
template <int P>
__device__ __forceinline__ void run_patch(
    const float* __restrict__ x, const float* __restrict__ Wk,
    float* __restrict__ out, float* __restrict__ mask_out, float (*sv)[32],
    int s, int b0, int c, int L, int S, int off, int total, int with_mask)
{
    constexpr int PP4 = (P + 3) & ~3;   // pad to multiple of 4 (zero slots)
    constexpr int NP2 = PP4 / 2;        // f32x2 pairs along t
    constexpr int NQ  = PP4 / 4;        // 16B quads along t
    int tid = threadIdx.x;

    // stage patch values (with zero padding) for Gm batch rows
    for (int i = tid; i < Gm * PP4; i += 256) {
        int g = i / PP4, t = i - g * PP4;
        float val = 0.0f;
        if (t < P && t < L) val = x[(size_t)(b0 + g) * NV + c + t];
        sv[g][t] = val;
    }

    // this block also writes its own slice of the padding mask
    if (with_mask) {
        for (int i = tid; i < Gm * P; i += 256) {
            int g = i / P, t = i - g * P;
            mask_out[(size_t)(b0 + g) * total + off + t] = (t >= L) ? 1.0f : 0.0f;
        }
    }

    int d = tid << 1;   // even -> 8B-aligned f2 loads/stores
    const float* rA = Wk + (size_t)d * P;
    const float* rB = rA + P;

    // load both W rows, zero-padded to PP4, then pack into 64-bit pairs (prologue only)
    float wa[PP4], wb[PP4];
#pragma unroll
    for (int t = 0; t < PP4; t++) { wa[t] = (t < P) ? rA[t] : 0.0f; wb[t] = (t < P) ? rB[t] : 0.0f; }

    unsigned long long wa2[NP2], wb2[NP2];
#pragma unroll
    for (int j = 0; j < NP2; j++) {
        asm("mov.b64 %0, {%1, %2};" : "=l"(wa2[j]) : "f"(wa[2 * j]), "f"(wa[2 * j + 1]));
        asm("mov.b64 %0, {%1, %2};" : "=l"(wb2[j]) : "f"(wb[2 * j]), "f"(wb[2 * j + 1]));
    }
    float2 pe2 = *(const float2*)(g_pe + s * DM + d);

    __syncthreads();

#pragma unroll 8
    for (int g = 0; g < Gm; g++) {
        unsigned long long aA0 = 0ull, aA1 = 0ull, aB0 = 0ull, aB1 = 0ull;
#pragma unroll
        for (int q = 0; q < NQ; q++) {
            ulonglong2 v = *reinterpret_cast<const ulonglong2*>(&sv[g][4 * q]);
            asm("fma.rn.f32x2 %0, %1, %2, %0;" : "+l"(aA0) : "l"(v.x), "l"(wa2[2 * q]));
            asm("fma.rn.f32x2 %0, %1, %2, %0;" : "+l"(aB0) : "l"(v.x), "l"(wb2[2 * q]));
            asm("fma.rn.f32x2 %0, %1, %2, %0;" : "+l"(aA1) : "l"(v.y), "l"(wa2[2 * q + 1]));
            asm("fma.rn.f32x2 %0, %1, %2, %0;" : "+l"(aB1) : "l"(v.y), "l"(wb2[2 * q + 1]));
        }
        float a0, a1, a2, a3, c0, c1, c2, c3;
        asm("mov.b64 {%0, %1}, %2;" : "=f"(a0), "=f"(a1) : "l"(aA0));
        asm("mov.b64 {%0, %1}, %2;" : "=f"(a2), "=f"(a3) : "l"(aA1));
        asm("mov.b64 {%0, %1}, %2;" : "=f"(c0), "=f"(c1) : "l"(aB0));
        asm("mov.b64 {%0, %1}, %2;" : "=f"(c2), "=f"(c3) : "l"(aB1));
        float2 o;
        o.x = (a0 + a1) + (a2 + a3) + pe2.x;
        o.y = (c0 + c1) + (c2 + c3) + pe2.y;
        *(float2*)(out + ((size_t)(b0 + g) * S + s) * DM + d) = o;
    }
}

__global__ void __launch_bounds__(256) embed_kernel(
    const float* __restrict__ x,
    const float* __restrict__ W0, const float* __restrict__ W1,
    const float* __restrict__ W2, const float* __restrict__ W3,
    float* __restrict__ out, int with_mask)
{
    __shared__ __align__(16) float sv[Gm][32];
    int s = blockIdx.y;
    int S = g_S;
    if (s >= S) return;
    int total = g_total;
    float* mask_out = out + (size_t)BB * S * DM;
    int b0 = blockIdx.x * Gm;
    int c = g_c[s], L = g_L[s], k = g_k[s], off = g_off[s];
    switch (k) {
        case 0:  run_patch<5 >(x, W0, out, mask_out, sv, s, b0, c, L, S, off, total, with_mask); break;
        case 1:  run_patch<10>(x, W1, out, mask_out, sv, s, b0, c, L, S, off, total, with_mask); break;
        case 2:  run_patch<17>(x, W2, out, mask_out, sv, s, b0, c, L, S, off, total, with_mask); break;
        default: run_patch<24>(x, W3, out, mask_out, sv, s, b0, c, L, S, off, total, with_mask); break;
    }
}

// ---------------- launch --------------------------------------------------------
extern "C" void kernel_launch(void* const* d_in, const int* in_sizes, int n_in,
                              void* d_out, int out_size) {
    const float* x   = (const float*)d_in[0];
    const int*   seg = (const int*)  d_in[1];
    const float* W0  = (const float*)d_in[2];
    const float* W1  = (const float*)d_in[3];
    const float* W2  = (const float*)d_in[4];
    const float* W3  = (const float*)d_in[5];
    float* out = (float*)d_out;

    // If the harness concatenates (out, mask) the total is not a multiple of B*D.
    int with_mask = (out_size % (BB * DM)) != 0;

    setup_kernel<<<MAXS + 1, 256>>>(seg);
    dim3 grid(BB / Gm, MAXS);
    embed_kernel<<<grid, 256>>>(x, W0, W1, W2, W3, out, with_mask);
    (void)in_sizes; (void)n_in;
}

// round 7
// speedup vs baseline: 1.0247x; 1.0247x over previous
#include <cuda_runtime.h>
#include <math.h>

#define BB   256     // batch
#define DM   512     // d_model
#define NV   1376    // n_vars
#define Gm   64      // batch rows per block
#define MAXS 128     // max slots supported (actual S = 96)

// ---------------- device-global scratch (no allocations allowed) ----------------
__device__ int g_S, g_total;
__device__ int g_c[MAXS], g_L[MAXS], g_k[MAXS], g_off[MAXS];
__device__ float g_pe[MAXS * DM];

// ---------------- setup: block 0 = plan, blocks 1..MAXS = positional emb -------
__global__ void setup_kernel(const int* __restrict__ seg) {
    if (blockIdx.x == 0) {
        __shared__ int sc[MAXS], sL[MAXS], sk[MAXS], sPl[MAXS], soff[MAXS];
        __shared__ int sFirstNeg, sS;
        int tid = threadIdx.x;
        if (tid == 0) { sFirstNeg = NV; sS = 0; }
        __syncthreads();
        for (int t = tid; t < NV; t += blockDim.x)
            if (seg[t] < 0) atomicMin(&sFirstNeg, t);
        __syncthreads();
        int validN = sFirstNeg;
        for (int t = tid; t < validN; t += blockDim.x) {
            int v = seg[t];
            int prev = (t == 0) ? -2 : seg[t - 1];
            if (v != prev) sc[v] = t;
            atomicMax(&sS, v + 1);
        }
        __syncthreads();
        int S = sS;
        const int PL[4] = {5, 10, 17, 24};
        for (int s = tid; s < S; s += blockDim.x) {
            int cs = sc[s];
            int L = ((s + 1 < S) ? sc[s + 1] : validN) - cs;
            int bestk = 0, bd = abs(L - PL[0]);
#pragma unroll
            for (int k = 1; k < 4; k++) {
                int dd = abs(L - PL[k]);
                if (dd < bd) { bd = dd; bestk = k; }   // strict < keeps first on tie
            }
            sL[s] = L; sk[s] = bestk; sPl[s] = PL[bestk];
        }
        __syncthreads();
        if (tid == 0) {
            int acc = 0;
            for (int s = 0; s < S; s++) { soff[s] = acc; acc += sPl[s]; }
            g_total = acc;
            g_S = S;
        }
        __syncthreads();
        for (int s = tid; s < S; s += blockDim.x) {
            g_c[s] = sc[s]; g_L[s] = sL[s]; g_k[s] = sk[s]; g_off[s] = soff[s];
        }
    } else {
        int s = blockIdx.x - 1;
        int j = threadIdx.x;                       // 0..255
        float freq = expf(-(float)(2 * j) * (logf(10000.0f) / (float)DM));
        float sv, cv;
        sincosf((float)s * freq, &sv, &cv);
        g_pe[s * DM + 2 * j]     = sv;
        g_pe[s * DM + 2 * j + 1] = cv;
    }
}

// ---------------- main embedding -----------------------------------------------
// One block = (slot s, 64 batch rows, one 256-channel half of d_model).
// 256 threads, each owns ONE output channel d = dbase + tid, so the per-thread
// W footprint is <= 12 packed f32x2 pairs (~24 regs) -> 5 blocks/SM resident.
// Patch values staged once in shared (zero padded to a multiple of 4) and read
// as LDS.128 broadcast, feeding fma.rn.f32x2 on 2 accumulator chains.
template <int P>
__device__ __forceinline__ void run_patch(
    const float* __restrict__ x, const float* __restrict__ Wk,
    float* __restrict__ out, float* __restrict__ mask_out, float (*sv)[32],
    int s, int b0, int dbase, int c, int L, int S, int off, int total, int write_mask)
{
    constexpr int PP4 = (P + 3) & ~3;   // pad to multiple of 4 (zero slots)
    constexpr int NP2 = PP4 / 2;        // f32x2 pairs along t
    constexpr int NQ  = PP4 / 4;        // 16B quads along t
    int tid = threadIdx.x;

    // stage patch values (with zero padding) for Gm batch rows
#pragma unroll
    for (int i = tid; i < Gm * PP4; i += 256) {
        int g = i / PP4, t = i - g * PP4;
        float val = 0.0f;
        if (t < P && t < L) val = x[(size_t)(b0 + g) * NV + c + t];
        sv[g][t] = val;
    }

    // d-half 0 writes this (s, b-group)'s slice of the padding mask
    if (write_mask) {
#pragma unroll
        for (int i = tid; i < Gm * P; i += 256) {
            int g = i / P, t = i - g * P;
            mask_out[(size_t)(b0 + g) * total + off + t] = (t >= L) ? 1.0f : 0.0f;
        }
    }

    int d = dbase + tid;
    const float* rW = Wk + (size_t)d * P;

    float w[PP4];
#pragma unroll
    for (int t = 0; t < PP4; t++) w[t] = (t < P) ? __ldg(rW + t) : 0.0f;

    unsigned long long w2[NP2];
#pragma unroll
    for (int j = 0; j < NP2; j++)
        asm("mov.b64 %0, {%1, %2};" : "=l"(w2[j]) : "f"(w[2 * j]), "f"(w[2 * j + 1]));

    float pe = g_pe[s * DM + d];

    __syncthreads();

    float* op = out + ((size_t)b0 * S + s) * DM + d;
    const size_t ostride = (size_t)S * DM;

#pragma unroll 4
    for (int g = 0; g < Gm; g++) {
        unsigned long long a0 = 0ull, a1 = 0ull;
#pragma unroll
        for (int q = 0; q < NQ; q++) {
            ulonglong2 v = *reinterpret_cast<const ulonglong2*>(&sv[g][4 * q]);
            asm("fma.rn.f32x2 %0, %1, %2, %0;" : "+l"(a0) : "l"(v.x), "l"(w2[2 * q]));
            asm("fma.rn.f32x2 %0, %1, %2, %0;" : "+l"(a1) : "l"(v.y), "l"(w2[2 * q + 1]));
        }
        float f0, f1, f2, f3;
        asm("mov.b64 {%0, %1}, %2;" : "=f"(f0), "=f"(f1) : "l"(a0));
        asm("mov.b64 {%0, %1}, %2;" : "=f"(f2), "=f"(f3) : "l"(a1));
        op[(size_t)g * ostride] = (f0 + f1) + (f2 + f3) + pe;
    }
}

__global__ void __launch_bounds__(256, 5) embed_kernel(
    const float* __restrict__ x,
    const float* __restrict__ W0, const float* __restrict__ W1,
    const float* __restrict__ W2, const float* __restrict__ W3,
    float* __restrict__ out, int with_mask)
{
    __shared__ __align__(16) float sv[Gm][32];
    int s = blockIdx.y;
    int S = g_S;
    if (s >= S) return;
    int total = g_total;
    float* mask_out = out + (size_t)BB * S * DM;
    int bgroup = blockIdx.x >> 1;
    int dhalf  = blockIdx.x & 1;
    int b0 = bgroup * Gm;
    int dbase = dhalf * 256;
    int write_mask = with_mask && (dhalf == 0);
    int c = g_c[s], L = g_L[s], k = g_k[s], off = g_off[s];
    switch (k) {
        case 0:  run_patch<5 >(x, W0, out, mask_out, sv, s, b0, dbase, c, L, S, off, total, write_mask); break;
        case 1:  run_patch<10>(x, W1, out, mask_out, sv, s, b0, dbase, c, L, S, off, total, write_mask); break;
        case 2:  run_patch<17>(x, W2, out, mask_out, sv, s, b0, dbase, c, L, S, off, total, write_mask); break;
        default: run_patch<24>(x, W3, out, mask_out, sv, s, b0, dbase, c, L, S, off, total, write_mask); break;
    }
}

// ---------------- launch --------------------------------------------------------
extern "C" void kernel_launch(void* const* d_in, const int* in_sizes, int n_in,
                              void* d_out, int out_size) {
    const float* x   = (const float*)d_in[0];
    const int*   seg = (const int*)  d_in[1];
    const float* W0  = (const float*)d_in[2];
    const float* W1  = (const float*)d_in[3];
    const float* W2  = (const float*)d_in[4];
    const float* W3  = (const float*)d_in[5];
    float* out = (float*)d_out;

    // If the harness concatenates (out, mask) the total is not a multiple of B*D.
    int with_mask = (out_size % (BB * DM)) != 0;

    setup_kernel<<<MAXS + 1, 256>>>(seg);
    dim3 grid((BB / Gm) * 2, MAXS);   // 8 x 128 (96 active slots -> 768 work blocks)
    embed_kernel<<<grid, 256>>>(x, W0, W1, W2, W3, out, with_mask);
    (void)in_sizes; (void)n_in;
}